// round 4
// baseline (speedup 1.0000x reference)
#include <cuda_runtime.h>
#include <math.h>

#define S_LEN 2048
#define BATCH 4
#define NH    12
#define DK    64
#define DM    768
#define ROWS  (BATCH*S_LEN)   // 8192

// Scratch (allocation-free rule: __device__ globals)
__device__ float g_q[(size_t)BATCH*NH*S_LEN*DK];
__device__ float g_k[(size_t)BATCH*NH*S_LEN*DK];
__device__ float g_v[(size_t)BATCH*NH*S_LEN*DK];
__device__ float g_attn[(size_t)ROWS*DM];

// ---------------------------------------------------------------------------
// 128x128x8 double-buffered SGEMM body. C = A(8192xDM) @ W(DMxDM) + bias.
// mode 0: scatter to (B,H,S,DK) head layout. mode 1: flat row-major.
// ---------------------------------------------------------------------------
__device__ __forceinline__ void gemm_body(const float* __restrict__ A,
                                          const float* __restrict__ W,
                                          const float* __restrict__ bias,
                                          float* __restrict__ dst,
                                          int mode)
{
    __shared__ __align__(16) float As[2][8][128];
    __shared__ __align__(16) float Bs[2][8][128];

    const int tid  = threadIdx.x;
    const int tx   = tid & 15;          // 16 col groups of 8
    const int ty   = tid >> 4;          // 16 row groups of 8
    const int aRow = tid >> 1;          // 0..127
    const int aCol = (tid & 1) * 4;     // 0 or 4
    const int bRow = tid >> 5;          // 0..7
    const int bCol = (tid & 31) * 4;    // 0..124

    const float* Aptr = A + (size_t)(blockIdx.x * 128 + aRow) * DM + aCol;
    const float* Bptr = W + (size_t)bRow * DM + blockIdx.y * 128 + bCol;

    // preload tile 0
    {
        float4 a = *(const float4*)Aptr;
        As[0][aCol + 0][aRow] = a.x;
        As[0][aCol + 1][aRow] = a.y;
        As[0][aCol + 2][aRow] = a.z;
        As[0][aCol + 3][aRow] = a.w;
        float4 b = *(const float4*)Bptr;
        *(float4*)&Bs[0][bRow][bCol] = b;
    }
    __syncthreads();

    float acc[8][8];
#pragma unroll
    for (int i = 0; i < 8; i++)
#pragma unroll
        for (int j = 0; j < 8; j++) acc[i][j] = 0.f;

    int cur = 0;
    for (int k0 = 0; k0 < DM; k0 += 8) {
        const bool has_next = (k0 + 8) < DM;
        float4 an, bn;
        if (has_next) {
            an = *(const float4*)(Aptr + (k0 + 8));
            bn = *(const float4*)(Bptr + (size_t)(k0 + 8) * DM);
        }
#pragma unroll
        for (int kk = 0; kk < 8; kk++) {
            float a[8], b[8];
            *(float4*)(a)     = *(float4*)&As[cur][kk][ty * 8];
            *(float4*)(a + 4) = *(float4*)&As[cur][kk][ty * 8 + 4];
            *(float4*)(b)     = *(float4*)&Bs[cur][kk][tx * 8];
            *(float4*)(b + 4) = *(float4*)&Bs[cur][kk][tx * 8 + 4];
#pragma unroll
            for (int i = 0; i < 8; i++)
#pragma unroll
                for (int j = 0; j < 8; j++)
                    acc[i][j] += a[i] * b[j];
        }
        if (has_next) {
            As[cur ^ 1][aCol + 0][aRow] = an.x;
            As[cur ^ 1][aCol + 1][aRow] = an.y;
            As[cur ^ 1][aCol + 2][aRow] = an.z;
            As[cur ^ 1][aCol + 3][aRow] = an.w;
            *(float4*)&Bs[cur ^ 1][bRow][bCol] = bn;
        }
        __syncthreads();
        cur ^= 1;
    }

    const int row0 = blockIdx.x * 128 + ty * 8;
    const int col0 = blockIdx.y * 128 + tx * 8;

    float bv[8];
    *(float4*)(bv)     = *(const float4*)(bias + col0);
    *(float4*)(bv + 4) = *(const float4*)(bias + col0 + 4);

    if (mode == 0) {
        // scatter into (B,H,S,DK): col0..col0+7 lie within one head (8 | 64)
        const int h  = col0 >> 6;
        const int d0 = col0 & 63;
#pragma unroll
        for (int i = 0; i < 8; i++) {
            const int row = row0 + i;
            const int bb  = row >> 11;     // /2048
            const int ss  = row & 2047;
            float* p = dst + ((((size_t)bb * NH + h) * S_LEN + ss) * DK + d0);
            float4 v0 = make_float4(acc[i][0] + bv[0], acc[i][1] + bv[1],
                                    acc[i][2] + bv[2], acc[i][3] + bv[3]);
            float4 v1 = make_float4(acc[i][4] + bv[4], acc[i][5] + bv[5],
                                    acc[i][6] + bv[6], acc[i][7] + bv[7]);
            *(float4*)(p)     = v0;
            *(float4*)(p + 4) = v1;
        }
    } else {
#pragma unroll
        for (int i = 0; i < 8; i++) {
            float* p = dst + (size_t)(row0 + i) * DM + col0;
            float4 v0 = make_float4(acc[i][0] + bv[0], acc[i][1] + bv[1],
                                    acc[i][2] + bv[2], acc[i][3] + bv[3]);
            float4 v1 = make_float4(acc[i][4] + bv[4], acc[i][5] + bv[5],
                                    acc[i][6] + bv[6], acc[i][7] + bv[7]);
            *(float4*)(p)     = v0;
            *(float4*)(p + 4) = v1;
        }
    }
}

__global__ __launch_bounds__(256) void gemm_qkv_kernel(
    const float* __restrict__ x,
    const float* __restrict__ Wq, const float* __restrict__ bq,
    const float* __restrict__ Wk, const float* __restrict__ bk,
    const float* __restrict__ Wv, const float* __restrict__ bv)
{
    const float* W; const float* bias; float* dst;
    if (blockIdx.z == 0)      { W = Wq; bias = bq; dst = g_q; }
    else if (blockIdx.z == 1) { W = Wk; bias = bk; dst = g_k; }
    else                      { W = Wv; bias = bv; dst = g_v; }
    gemm_body(x, W, bias, dst, 0);
}

__global__ __launch_bounds__(256) void gemm_out_kernel(
    const float* __restrict__ Wo, const float* __restrict__ bo,
    float* __restrict__ out)
{
    gemm_body(g_attn, Wo, bo, out, 1);
}

// ---------------------------------------------------------------------------
// Flash attention: block = (query tile of 64, b*h). Key tiles of 32.
// Online softmax; causal tiles beyond the diagonal are skipped entirely.
// ---------------------------------------------------------------------------
__global__ __launch_bounds__(256) void attn_kernel()
{
    __shared__ float Qs[64][65];
    __shared__ float Ks[32][65];
    __shared__ float Vs[32][65];
    __shared__ float Ss[64][33];
    __shared__ float sm_m[64], sm_l[64], sm_alpha[64];

    const int tid = threadIdx.x;
    const int qt  = blockIdx.x;   // 0..31
    const int bh  = blockIdx.y;   // 0..47

    const float* qp = g_q + ((size_t)bh * S_LEN + qt * 64) * DK;
    const float* kp = g_k + (size_t)bh * S_LEN * DK;
    const float* vp = g_v + (size_t)bh * S_LEN * DK;

    // load Q tile (64x64)
#pragma unroll
    for (int r = 0; r < 4; r++) {
        int idx = tid + r * 256;
        int i   = idx >> 4;
        int dq  = (idx & 15) * 4;
        float4 v = *(const float4*)(qp + i * DK + dq);
        Qs[i][dq] = v.x; Qs[i][dq + 1] = v.y; Qs[i][dq + 2] = v.z; Qs[i][dq + 3] = v.w;
    }
    if (tid < 64) { sm_m[tid] = -1e30f; sm_l[tid] = 0.f; }

    const int tx = tid & 15, ty = tid >> 4;   // GEMM thread grid 16x16
    const int srow = tid >> 2, sq = tid & 3;  // softmax: 4 threads/row, 8 cols each

    float o[4][4];
#pragma unroll
    for (int u = 0; u < 4; u++)
#pragma unroll
        for (int v = 0; v < 4; v++) o[u][v] = 0.f;

    const int nkt = 2 * qt + 2;
    for (int kt = 0; kt < nkt; kt++) {
        __syncthreads();   // prev iteration done reading Ks/Vs/Ss

        // load K,V key tile (32x64 each)
#pragma unroll
        for (int r = 0; r < 2; r++) {
            int idx = tid + r * 256;
            int j   = idx >> 4;
            int dq  = (idx & 15) * 4;
            float4 kv = *(const float4*)(kp + ((size_t)kt * 32 + j) * DK + dq);
            Ks[j][dq] = kv.x; Ks[j][dq + 1] = kv.y; Ks[j][dq + 2] = kv.z; Ks[j][dq + 3] = kv.w;
            float4 vv = *(const float4*)(vp + ((size_t)kt * 32 + j) * DK + dq);
            Vs[j][dq] = vv.x; Vs[j][dq + 1] = vv.y; Vs[j][dq + 2] = vv.z; Vs[j][dq + 3] = vv.w;
        }
        __syncthreads();

        // S = Q @ K^T * 0.125  (each thread: 4 rows x 2 cols)
        float c[4][2] = {{0.f,0.f},{0.f,0.f},{0.f,0.f},{0.f,0.f}};
#pragma unroll 16
        for (int dd = 0; dd < 64; dd++) {
            float a0 = Qs[ty * 4 + 0][dd];
            float a1 = Qs[ty * 4 + 1][dd];
            float a2 = Qs[ty * 4 + 2][dd];
            float a3 = Qs[ty * 4 + 3][dd];
            float b0 = Ks[tx * 2 + 0][dd];
            float b1 = Ks[tx * 2 + 1][dd];
            c[0][0] += a0 * b0; c[0][1] += a0 * b1;
            c[1][0] += a1 * b0; c[1][1] += a1 * b1;
            c[2][0] += a2 * b0; c[2][1] += a2 * b1;
            c[3][0] += a3 * b0; c[3][1] += a3 * b1;
        }
        const bool need_mask = (kt >= 2 * qt);
#pragma unroll
        for (int u = 0; u < 4; u++)
#pragma unroll
            for (int v = 0; v < 2; v++) {
                float s = c[u][v] * 0.125f;
                if (need_mask) {
                    int gi = qt * 64 + ty * 4 + u;
                    int gj = kt * 32 + tx * 2 + v;
                    if (gj > gi) s = -1e30f;
                }
                Ss[ty * 4 + u][tx * 2 + v] = s;
            }
        __syncthreads();

        // online softmax (row-wise over this 64x32 tile)
        float sv[8];
        float mloc = -1e30f;
#pragma unroll
        for (int cidx = 0; cidx < 8; cidx++) {
            sv[cidx] = Ss[srow][sq * 8 + cidx];
            mloc = fmaxf(mloc, sv[cidx]);
        }
        mloc = fmaxf(mloc, __shfl_xor_sync(0xffffffffu, mloc, 1));
        mloc = fmaxf(mloc, __shfl_xor_sync(0xffffffffu, mloc, 2));
        const float mold = sm_m[srow];
        const float mnew = fmaxf(mold, mloc);
        float lsum = 0.f;
#pragma unroll
        for (int cidx = 0; cidx < 8; cidx++) {
            float p = __expf(sv[cidx] - mnew);
            Ss[srow][sq * 8 + cidx] = p;
            lsum += p;
        }
        lsum += __shfl_xor_sync(0xffffffffu, lsum, 1);
        lsum += __shfl_xor_sync(0xffffffffu, lsum, 2);
        if (sq == 0) {
            float alpha = __expf(mold - mnew);
            sm_alpha[srow] = alpha;
            sm_m[srow]     = mnew;
            sm_l[srow]     = sm_l[srow] * alpha + lsum;
        }
        __syncthreads();

        // rescale accumulator and do O += P @ V  (each thread: 4 rows x 4 d)
        float al[4];
#pragma unroll
        for (int u = 0; u < 4; u++) al[u] = sm_alpha[ty * 4 + u];
#pragma unroll
        for (int u = 0; u < 4; u++)
#pragma unroll
            for (int v = 0; v < 4; v++) o[u][v] *= al[u];

#pragma unroll 8
        for (int jj = 0; jj < 32; jj++) {
            float p0 = Ss[ty * 4 + 0][jj];
            float p1 = Ss[ty * 4 + 1][jj];
            float p2 = Ss[ty * 4 + 2][jj];
            float p3 = Ss[ty * 4 + 3][jj];
            float w0 = Vs[jj][tx * 4 + 0];
            float w1 = Vs[jj][tx * 4 + 1];
            float w2 = Vs[jj][tx * 4 + 2];
            float w3 = Vs[jj][tx * 4 + 3];
            o[0][0] += p0 * w0; o[0][1] += p0 * w1; o[0][2] += p0 * w2; o[0][3] += p0 * w3;
            o[1][0] += p1 * w0; o[1][1] += p1 * w1; o[1][2] += p1 * w2; o[1][3] += p1 * w3;
            o[2][0] += p2 * w0; o[2][1] += p2 * w1; o[2][2] += p2 * w2; o[2][3] += p2 * w3;
            o[3][0] += p3 * w0; o[3][1] += p3 * w1; o[3][2] += p3 * w2; o[3][3] += p3 * w3;
        }
    }

    // epilogue: normalize and write (B,S,H*DK) row-major for the output GEMM
    const int b = bh / NH, h = bh % NH;
#pragma unroll
    for (int u = 0; u < 4; u++) {
        const float invl = 1.0f / sm_l[ty * 4 + u];
        const int sg = qt * 64 + ty * 4 + u;
        float* outp = g_attn + ((size_t)(b * S_LEN + sg)) * DM + h * DK + tx * 4;
        float4 res = make_float4(o[u][0] * invl, o[u][1] * invl,
                                 o[u][2] * invl, o[u][3] * invl);
        *(float4*)outp = res;
    }
}

// ---------------------------------------------------------------------------
extern "C" void kernel_launch(void* const* d_in, const int* in_sizes, int n_in,
                              void* d_out, int out_size)
{
    const float* x  = (const float*)d_in[0];
    const float* Wq = (const float*)d_in[1];
    const float* bq = (const float*)d_in[2];
    const float* Wk = (const float*)d_in[3];
    const float* bk = (const float*)d_in[4];
    const float* Wv = (const float*)d_in[5];
    const float* bv = (const float*)d_in[6];
    const float* Wo = (const float*)d_in[7];
    const float* bo = (const float*)d_in[8];
    float* out = (float*)d_out;

    dim3 gqkv(ROWS / 128, DM / 128, 3);
    gemm_qkv_kernel<<<gqkv, 256>>>(x, Wq, bq, Wk, bk, Wv, bv);

    dim3 gattn(S_LEN / 64, BATCH * NH);
    attn_kernel<<<gattn, 256>>>();

    dim3 gout(ROWS / 128, DM / 128);
    gemm_out_kernel<<<gout, 256>>>(Wo, bo, out);
}

// round 6
// speedup vs baseline: 1.0076x; 1.0076x over previous
#include <cuda_runtime.h>
#include <math.h>

#define S_LEN 2048
#define BATCH 4
#define NH    12
#define DK    64
#define DM    768
#define ROWS  (BATCH*S_LEN)   // 8192

// Scratch (allocation-free rule: __device__ globals)
__device__ float g_q[(size_t)BATCH*NH*S_LEN*DK];
__device__ float g_k[(size_t)BATCH*NH*S_LEN*DK];
__device__ float g_v[(size_t)BATCH*NH*S_LEN*DK];
__device__ float g_attn[(size_t)ROWS*DM];

// ---------------------------------------------------------------------------
// 128x128x8 double-buffered SGEMM body. C = A(8192xDM) @ W(DMxDM) + bias.
// mode 0: scatter to (B,H,S,DK) head layout. mode 1: flat row-major.
// ---------------------------------------------------------------------------
__device__ __forceinline__ void gemm_body(const float* __restrict__ A,
                                          const float* __restrict__ W,
                                          const float* __restrict__ bias,
                                          float* __restrict__ dst,
                                          int mode)
{
    __shared__ __align__(16) float As[2][8][128];
    __shared__ __align__(16) float Bs[2][8][128];

    const int tid  = threadIdx.x;
    const int tx   = tid & 15;          // 16 col groups of 8
    const int ty   = tid >> 4;          // 16 row groups of 8
    const int aRow = tid >> 1;          // 0..127
    const int aCol = (tid & 1) * 4;     // 0 or 4
    const int bRow = tid >> 5;          // 0..7
    const int bCol = (tid & 31) * 4;    // 0..124

    const float* Aptr = A + (size_t)(blockIdx.x * 128 + aRow) * DM + aCol;
    const float* Bptr = W + (size_t)bRow * DM + blockIdx.y * 128 + bCol;

    // preload tile 0
    {
        float4 a = *(const float4*)Aptr;
        As[0][aCol + 0][aRow] = a.x;
        As[0][aCol + 1][aRow] = a.y;
        As[0][aCol + 2][aRow] = a.z;
        As[0][aCol + 3][aRow] = a.w;
        float4 b = *(const float4*)Bptr;
        *(float4*)&Bs[0][bRow][bCol] = b;
    }
    __syncthreads();

    float acc[8][8];
#pragma unroll
    for (int i = 0; i < 8; i++)
#pragma unroll
        for (int j = 0; j < 8; j++) acc[i][j] = 0.f;

    int cur = 0;
    for (int k0 = 0; k0 < DM; k0 += 8) {
        const bool has_next = (k0 + 8) < DM;
        float4 an, bn;
        if (has_next) {
            an = *(const float4*)(Aptr + (k0 + 8));
            bn = *(const float4*)(Bptr + (size_t)(k0 + 8) * DM);
        }
#pragma unroll
        for (int kk = 0; kk < 8; kk++) {
            float a[8], b[8];
            *(float4*)(a)     = *(float4*)&As[cur][kk][ty * 8];
            *(float4*)(a + 4) = *(float4*)&As[cur][kk][ty * 8 + 4];
            *(float4*)(b)     = *(float4*)&Bs[cur][kk][tx * 8];
            *(float4*)(b + 4) = *(float4*)&Bs[cur][kk][tx * 8 + 4];
#pragma unroll
            for (int i = 0; i < 8; i++)
#pragma unroll
                for (int j = 0; j < 8; j++)
                    acc[i][j] += a[i] * b[j];
        }
        if (has_next) {
            As[cur ^ 1][aCol + 0][aRow] = an.x;
            As[cur ^ 1][aCol + 1][aRow] = an.y;
            As[cur ^ 1][aCol + 2][aRow] = an.z;
            As[cur ^ 1][aCol + 3][aRow] = an.w;
            *(float4*)&Bs[cur ^ 1][bRow][bCol] = bn;
        }
        __syncthreads();
        cur ^= 1;
    }

    const int row0 = blockIdx.x * 128 + ty * 8;
    const int col0 = blockIdx.y * 128 + tx * 8;

    float bv[8];
    *(float4*)(bv)     = *(const float4*)(bias + col0);
    *(float4*)(bv + 4) = *(const float4*)(bias + col0 + 4);

    if (mode == 0) {
        // scatter into (B,H,S,DK): col0..col0+7 lie within one head (8 | 64)
        const int h  = col0 >> 6;
        const int d0 = col0 & 63;
#pragma unroll
        for (int i = 0; i < 8; i++) {
            const int row = row0 + i;
            const int bb  = row >> 11;     // /2048
            const int ss  = row & 2047;
            float* p = dst + ((((size_t)bb * NH + h) * S_LEN + ss) * DK + d0);
            float4 v0 = make_float4(acc[i][0] + bv[0], acc[i][1] + bv[1],
                                    acc[i][2] + bv[2], acc[i][3] + bv[3]);
            float4 v1 = make_float4(acc[i][4] + bv[4], acc[i][5] + bv[5],
                                    acc[i][6] + bv[6], acc[i][7] + bv[7]);
            *(float4*)(p)     = v0;
            *(float4*)(p + 4) = v1;
        }
    } else {
#pragma unroll
        for (int i = 0; i < 8; i++) {
            float* p = dst + (size_t)(row0 + i) * DM + col0;
            float4 v0 = make_float4(acc[i][0] + bv[0], acc[i][1] + bv[1],
                                    acc[i][2] + bv[2], acc[i][3] + bv[3]);
            float4 v1 = make_float4(acc[i][4] + bv[4], acc[i][5] + bv[5],
                                    acc[i][6] + bv[6], acc[i][7] + bv[7]);
            *(float4*)(p)     = v0;
            *(float4*)(p + 4) = v1;
        }
    }
}

__global__ __launch_bounds__(256) void gemm_qkv_kernel(
    const float* __restrict__ x,
    const float* __restrict__ Wq, const float* __restrict__ bq,
    const float* __restrict__ Wk, const float* __restrict__ bk,
    const float* __restrict__ Wv, const float* __restrict__ bv)
{
    const float* W; const float* bias; float* dst;
    if (blockIdx.z == 0)      { W = Wq; bias = bq; dst = g_q; }
    else if (blockIdx.z == 1) { W = Wk; bias = bk; dst = g_k; }
    else                      { W = Wv; bias = bv; dst = g_v; }
    gemm_body(x, W, bias, dst, 0);
}

__global__ __launch_bounds__(256) void gemm_out_kernel(
    const float* __restrict__ Wo, const float* __restrict__ bo,
    float* __restrict__ out)
{
    gemm_body(g_attn, Wo, bo, out, 1);
}

// ---------------------------------------------------------------------------
// Flash attention: block = (query tile of 64, b*h). Key tiles of 32.
// Online softmax; causal tiles beyond the diagonal are skipped entirely.
// ---------------------------------------------------------------------------
__global__ __launch_bounds__(256) void attn_kernel()
{
    __shared__ float Qs[64][65];
    __shared__ float Ks[32][65];
    __shared__ float Vs[32][65];
    __shared__ float Ss[64][33];
    __shared__ float sm_m[64], sm_l[64], sm_alpha[64];

    const int tid = threadIdx.x;
    const int qt  = blockIdx.x;   // 0..31
    const int bh  = blockIdx.y;   // 0..47

    const float* qp = g_q + ((size_t)bh * S_LEN + qt * 64) * DK;
    const float* kp = g_k + (size_t)bh * S_LEN * DK;
    const float* vp = g_v + (size_t)bh * S_LEN * DK;

    // load Q tile (64x64)
#pragma unroll
    for (int r = 0; r < 4; r++) {
        int idx = tid + r * 256;
        int i   = idx >> 4;
        int dq  = (idx & 15) * 4;
        float4 v = *(const float4*)(qp + i * DK + dq);
        Qs[i][dq] = v.x; Qs[i][dq + 1] = v.y; Qs[i][dq + 2] = v.z; Qs[i][dq + 3] = v.w;
    }
    if (tid < 64) { sm_m[tid] = -1e30f; sm_l[tid] = 0.f; }

    const int tx = tid & 15, ty = tid >> 4;   // GEMM thread grid 16x16
    const int srow = tid >> 2, sq = tid & 3;  // softmax: 4 threads/row, 8 cols each

    float o[4][4];
#pragma unroll
    for (int u = 0; u < 4; u++)
#pragma unroll
        for (int v = 0; v < 4; v++) o[u][v] = 0.f;

    const int nkt = 2 * qt + 2;
    for (int kt = 0; kt < nkt; kt++) {
        __syncthreads();   // prev iteration done reading Ks/Vs/Ss

        // load K,V key tile (32x64 each)
#pragma unroll
        for (int r = 0; r < 2; r++) {
            int idx = tid + r * 256;
            int j   = idx >> 4;
            int dq  = (idx & 15) * 4;
            float4 kv = *(const float4*)(kp + ((size_t)kt * 32 + j) * DK + dq);
            Ks[j][dq] = kv.x; Ks[j][dq + 1] = kv.y; Ks[j][dq + 2] = kv.z; Ks[j][dq + 3] = kv.w;
            float4 vv = *(const float4*)(vp + ((size_t)kt * 32 + j) * DK + dq);
            Vs[j][dq] = vv.x; Vs[j][dq + 1] = vv.y; Vs[j][dq + 2] = vv.z; Vs[j][dq + 3] = vv.w;
        }
        __syncthreads();

        // S = Q @ K^T * 0.125  (each thread: 4 rows x 2 cols)
        float c[4][2] = {{0.f,0.f},{0.f,0.f},{0.f,0.f},{0.f,0.f}};
#pragma unroll 16
        for (int dd = 0; dd < 64; dd++) {
            float a0 = Qs[ty * 4 + 0][dd];
            float a1 = Qs[ty * 4 + 1][dd];
            float a2 = Qs[ty * 4 + 2][dd];
            float a3 = Qs[ty * 4 + 3][dd];
            float b0 = Ks[tx * 2 + 0][dd];
            float b1 = Ks[tx * 2 + 1][dd];
            c[0][0] += a0 * b0; c[0][1] += a0 * b1;
            c[1][0] += a1 * b0; c[1][1] += a1 * b1;
            c[2][0] += a2 * b0; c[2][1] += a2 * b1;
            c[3][0] += a3 * b0; c[3][1] += a3 * b1;
        }
        const bool need_mask = (kt >= 2 * qt);
#pragma unroll
        for (int u = 0; u < 4; u++)
#pragma unroll
            for (int v = 0; v < 2; v++) {
                float s = c[u][v] * 0.125f;
                if (need_mask) {
                    int gi = qt * 64 + ty * 4 + u;
                    int gj = kt * 32 + tx * 2 + v;
                    if (gj > gi) s = -1e30f;
                }
                Ss[ty * 4 + u][tx * 2 + v] = s;
            }
        __syncthreads();

        // online softmax (row-wise over this 64x32 tile)
        float sv[8];
        float mloc = -1e30f;
#pragma unroll
        for (int cidx = 0; cidx < 8; cidx++) {
            sv[cidx] = Ss[srow][sq * 8 + cidx];
            mloc = fmaxf(mloc, sv[cidx]);
        }
        mloc = fmaxf(mloc, __shfl_xor_sync(0xffffffffu, mloc, 1));
        mloc = fmaxf(mloc, __shfl_xor_sync(0xffffffffu, mloc, 2));
        const float mold = sm_m[srow];
        const float mnew = fmaxf(mold, mloc);
        float lsum = 0.f;
#pragma unroll
        for (int cidx = 0; cidx < 8; cidx++) {
            float p = __expf(sv[cidx] - mnew);
            Ss[srow][sq * 8 + cidx] = p;
            lsum += p;
        }
        lsum += __shfl_xor_sync(0xffffffffu, lsum, 1);
        lsum += __shfl_xor_sync(0xffffffffu, lsum, 2);
        if (sq == 0) {
            float alpha = __expf(mold - mnew);
            sm_alpha[srow] = alpha;
            sm_m[srow]     = mnew;
            sm_l[srow]     = sm_l[srow] * alpha + lsum;
        }
        __syncthreads();

        // rescale accumulator and do O += P @ V  (each thread: 4 rows x 4 d)
        float al[4];
#pragma unroll
        for (int u = 0; u < 4; u++) al[u] = sm_alpha[ty * 4 + u];
#pragma unroll
        for (int u = 0; u < 4; u++)
#pragma unroll
            for (int v = 0; v < 4; v++) o[u][v] *= al[u];

#pragma unroll 8
        for (int jj = 0; jj < 32; jj++) {
            float p0 = Ss[ty * 4 + 0][jj];
            float p1 = Ss[ty * 4 + 1][jj];
            float p2 = Ss[ty * 4 + 2][jj];
            float p3 = Ss[ty * 4 + 3][jj];
            float w0 = Vs[jj][tx * 4 + 0];
            float w1 = Vs[jj][tx * 4 + 1];
            float w2 = Vs[jj][tx * 4 + 2];
            float w3 = Vs[jj][tx * 4 + 3];
            o[0][0] += p0 * w0; o[0][1] += p0 * w1; o[0][2] += p0 * w2; o[0][3] += p0 * w3;
            o[1][0] += p1 * w0; o[1][1] += p1 * w1; o[1][2] += p1 * w2; o[1][3] += p1 * w3;
            o[2][0] += p2 * w0; o[2][1] += p2 * w1; o[2][2] += p2 * w2; o[2][3] += p2 * w3;
            o[3][0] += p3 * w0; o[3][1] += p3 * w1; o[3][2] += p3 * w2; o[3][3] += p3 * w3;
        }
    }

    // epilogue: normalize and write (B,S,H*DK) row-major for the output GEMM
    const int b = bh / NH, h = bh % NH;
#pragma unroll
    for (int u = 0; u < 4; u++) {
        const float invl = 1.0f / sm_l[ty * 4 + u];
        const int sg = qt * 64 + ty * 4 + u;
        float* outp = g_attn + ((size_t)(b * S_LEN + sg)) * DM + h * DK + tx * 4;
        float4 res = make_float4(o[u][0] * invl, o[u][1] * invl,
                                 o[u][2] * invl, o[u][3] * invl);
        *(float4*)outp = res;
    }
}

// ---------------------------------------------------------------------------
extern "C" void kernel_launch(void* const* d_in, const int* in_sizes, int n_in,
                              void* d_out, int out_size)
{
    const float* x  = (const float*)d_in[0];
    const float* Wq = (const float*)d_in[1];
    const float* bq = (const float*)d_in[2];
    const float* Wk = (const float*)d_in[3];
    const float* bk = (const float*)d_in[4];
    const float* Wv = (const float*)d_in[5];
    const float* bv = (const float*)d_in[6];
    const float* Wo = (const float*)d_in[7];
    const float* bo = (const float*)d_in[8];
    float* out = (float*)d_out;

    dim3 gqkv(ROWS / 128, DM / 128, 3);
    gemm_qkv_kernel<<<gqkv, 256>>>(x, Wq, bq, Wk, bk, Wv, bv);

    dim3 gattn(S_LEN / 64, BATCH * NH);
    attn_kernel<<<gattn, 256>>>();

    dim3 gout(ROWS / 128, DM / 128);
    gemm_out_kernel<<<gout, 256>>>(Wo, bo, out);
}